// round 3
// baseline (speedup 1.0000x reference)
#include <cuda_runtime.h>
#include <cstdint>

// ---------------- problem constants ----------------
#define D_IN   2048
#define D_H    512
#define BN_EPS 1e-3f

// ---------------- GEMM tiling ----------------
#define BM 128
#define BN 128
#define KC 128                    // k-bytes (s8 elems) per smem chunk
#define NCHUNK (D_IN / KC)        // 16
#define NSTAGE 3
#define SMEM_DYN (NSTAGE * (BM * KC + BN * KC))   // 3 * 32KB = 96KB

// ---------------- device scratch ----------------
__device__ __align__(16) signed char g_Xq[(size_t)32768 * D_IN];  // 64 MB
__device__ __align__(16) signed char g_Wq[(size_t)D_H * D_IN];    // 1 MB, [n][k]
__device__ float g_alpha[D_H];
__device__ float g_cbias[D_H];

// ---------------- PTX helpers (sm_80-safe) ----------------
__device__ __forceinline__ uint32_t smem_u32(const void* p) {
    return (uint32_t)__cvta_generic_to_shared(p);
}
__device__ __forceinline__ void cp16(uint32_t s, const void* g) {
    asm volatile("cp.async.cg.shared.global [%0], [%1], 16;" :: "r"(s), "l"(g));
}
__device__ __forceinline__ void cp_commit() {
    asm volatile("cp.async.commit_group;" ::: "memory");
}
template <int N>
__device__ __forceinline__ void cp_wait() {
    asm volatile("cp.async.wait_group %0;" :: "n"(N) : "memory");
}
__device__ __forceinline__ uint32_t lds32(uint32_t addr) {
    uint32_t v;
    asm volatile("ld.shared.b32 %0, [%1];" : "=r"(v) : "r"(addr));
    return v;
}
__device__ __forceinline__ void mma_s8(int* c, const uint32_t* a,
                                       uint32_t b0, uint32_t b1) {
    asm volatile(
        "mma.sync.aligned.m16n8k32.row.col.s32.s8.s8.s32 "
        "{%0,%1,%2,%3}, {%4,%5,%6,%7}, {%8,%9}, {%0,%1,%2,%3};"
        : "+r"(c[0]), "+r"(c[1]), "+r"(c[2]), "+r"(c[3])
        : "r"(a[0]), "r"(a[1]), "r"(a[2]), "r"(a[3]), "r"(b0), "r"(b1));
}

// ---------------- prep: W transpose + sign + BN fold ----------------
__global__ __launch_bounds__(256)
void qdbn_prep_kernel(const float* __restrict__ W,
                      const float* __restrict__ b,
                      const float* __restrict__ beta,
                      const float* __restrict__ mean,
                      const float* __restrict__ var) {
    __shared__ signed char tile[32][33];
    const int n0 = blockIdx.x * 32;     // D_H/32 = 16 blocks
    const int k0 = blockIdx.y * 32;     // D_IN/32 = 64 blocks
    const int tx = threadIdx.x;         // 32
    const int ty = threadIdx.y;         // 8

    #pragma unroll
    for (int i = 0; i < 32; i += 8) {
        float w = W[(size_t)(k0 + ty + i) * D_H + (n0 + tx)];   // coalesced over n
        tile[ty + i][tx] = (w >= 0.0f) ? 1 : -1;                // tile[k][n]
    }
    __syncthreads();
    #pragma unroll
    for (int i = 0; i < 32; i += 8) {
        g_Wq[(size_t)(n0 + ty + i) * D_IN + (k0 + tx)] = tile[tx][ty + i];
    }

    if (blockIdx.x == 0 && blockIdx.y == 0) {
        int t = ty * 32 + tx;
        #pragma unroll
        for (int idx = t; idx < D_H; idx += 256) {
            float inv = rsqrtf(var[idx] + BN_EPS);
            g_alpha[idx] = inv;
            g_cbias[idx] = (b[idx] - mean[idx]) * inv + beta[idx];
        }
    }
}

// ---------------- pass 1: binarize X fp32 -> s8 ----------------
__device__ __forceinline__ uint32_t pk4(float4 v) {
    uint32_t r = (v.x >= 0.f) ? 0x01u : 0xFFu;
    r |= ((v.y >= 0.f) ? 0x01u : 0xFFu) << 8;
    r |= ((v.z >= 0.f) ? 0x01u : 0xFFu) << 16;
    r |= ((v.w >= 0.f) ? 0x01u : 0xFFu) << 24;
    return r;
}

__global__ __launch_bounds__(256)
void qdbn_binarize_kernel(const float4* __restrict__ X) {
    uint4* xq = reinterpret_cast<uint4*>(g_Xq);
    uint32_t i = blockIdx.x * 256u + threadIdx.x;   // one uint4 (16 s8) per thread
    const float4* p = X + (size_t)i * 4;
    uint4 o;
    o.x = pk4(p[0]);
    o.y = pk4(p[1]);
    o.z = pk4(p[2]);
    o.w = pk4(p[3]);
    xq[i] = o;
}

// ---------------- main GEMM (s8 IMMA) ----------------
// CTA: 128(M) x 128(N), 8 warps as 4(M) x 2(N) -> warp tile 32 x 64.
// smem layout per stage: A [128 rows][128B] then B [128 rows][128B],
// each row swizzled: 16B-granule g' = g ^ (row & 7).
__global__ __launch_bounds__(256)
void qdbn_imma_kernel(float* __restrict__ out) {
    extern __shared__ char dyn_smem[];
    const uint32_t base = smem_u32(dyn_smem);

    const int tid = threadIdx.x;
    const int wid = tid >> 5;
    const int lane = tid & 31;
    const int g = lane >> 2;          // group id 0..7
    const int t4 = (lane & 3) * 4;    // byte offset of thread-in-group
    const int m0 = blockIdx.y * BM;
    const int n0 = blockIdx.x * BN;
    const int wm = (wid >> 1) * 32;   // warp M offset in CTA tile
    const int wn = (wid & 1) * 64;    // warp N offset

    // stage s: A at base + s*32KB, B at base + s*32KB + 16KB
    uint32_t sA[NSTAGE], sB[NSTAGE];
    #pragma unroll
    for (int s = 0; s < NSTAGE; ++s) {
        sA[s] = base + s * (BM * KC + BN * KC);
        sB[s] = sA[s] + BM * KC;
    }

    // async loader: 8 x 16B granules per thread per chunk (4 A + 4 B)
    auto load_chunk = [&](int s, int c) {
        const size_t kbase = (size_t)c * KC;
        #pragma unroll
        for (int j = 0; j < 4; ++j) {
            int gid = j * 256 + tid;           // 0..1023
            int row = gid >> 3;
            int gr  = gid & 7;
            uint32_t dst = sA[s] + row * KC + ((gr ^ (row & 7)) << 4);
            cp16(dst, g_Xq + (size_t)(m0 + row) * D_IN + kbase + gr * 16);
        }
        #pragma unroll
        for (int j = 0; j < 4; ++j) {
            int gid = j * 256 + tid;
            int row = gid >> 3;
            int gr  = gid & 7;
            uint32_t dst = sB[s] + row * KC + ((gr ^ (row & 7)) << 4);
            cp16(dst, g_Wq + (size_t)(n0 + row) * D_IN + kbase + gr * 16);
        }
        cp_commit();
    };

    int acc[2][8][4];
    #pragma unroll
    for (int mf = 0; mf < 2; ++mf)
        #pragma unroll
        for (int nf = 0; nf < 8; ++nf)
            #pragma unroll
            for (int q = 0; q < 4; ++q) acc[mf][nf][q] = 0;

    // prologue: stages 0,1
    load_chunk(0, 0);
    load_chunk(1, 1);

    const uint32_t swz = (uint32_t)g << 4;   // rows in a frag all have (row&7)==g

    for (int c = 0; c < NCHUNK; ++c) {
        if (c + 2 < NCHUNK) load_chunk((c + 2) % NSTAGE, c + 2);

        const int rem = NCHUNK - 1 - c;
        if (rem >= 2)      cp_wait<2>();
        else if (rem == 1) cp_wait<1>();
        else               cp_wait<0>();
        __syncthreads();

        const uint32_t a_s = sA[c % NSTAGE];
        const uint32_t b_s = sB[c % NSTAGE];

        #pragma unroll
        for (int ks = 0; ks < 4; ++ks) {
            const uint32_t kk = ks * 32;
            uint32_t a[2][4];
            #pragma unroll
            for (int mf = 0; mf < 2; ++mf) {
                const int r0 = wm + mf * 16 + g;
                const int r1 = r0 + 8;
                a[mf][0] = lds32(a_s + r0 * KC + (kk ^ swz) + t4);
                a[mf][1] = lds32(a_s + r1 * KC + (kk ^ swz) + t4);
                a[mf][2] = lds32(a_s + r0 * KC + ((kk + 16) ^ swz) + t4);
                a[mf][3] = lds32(a_s + r1 * KC + ((kk + 16) ^ swz) + t4);
            }
            #pragma unroll
            for (int nf = 0; nf < 8; ++nf) {
                const int n = wn + nf * 8 + g;
                uint32_t b0 = lds32(b_s + n * KC + (kk ^ swz) + t4);
                uint32_t b1 = lds32(b_s + n * KC + ((kk + 16) ^ swz) + t4);
                mma_s8(acc[0][nf], a[0], b0, b1);
                mma_s8(acc[1][nf], a[1], b0, b1);
            }
        }
        __syncthreads();
    }

    // ---------------- epilogue: BN fold + store ----------------
    #pragma unroll
    for (int nf = 0; nf < 8; ++nf) {
        const int cn = n0 + wn + nf * 8 + (t4 >> 1);   // t*2
        const float al0 = g_alpha[cn],     cb0 = g_cbias[cn];
        const float al1 = g_alpha[cn + 1], cb1 = g_cbias[cn + 1];
        #pragma unroll
        for (int mf = 0; mf < 2; ++mf) {
            const int r0 = m0 + wm + mf * 16 + g;
            const int r1 = r0 + 8;
            float2 v0, v1;
            v0.x = (float)acc[mf][nf][0] * al0 + cb0;
            v0.y = (float)acc[mf][nf][1] * al1 + cb1;
            v1.x = (float)acc[mf][nf][2] * al0 + cb0;
            v1.y = (float)acc[mf][nf][3] * al1 + cb1;
            *(float2*)(out + (size_t)r0 * D_H + cn) = v0;
            *(float2*)(out + (size_t)r1 * D_H + cn) = v1;
        }
    }
}

// ---------------- launch ----------------
extern "C" void kernel_launch(void* const* d_in, const int* in_sizes, int n_in,
                              void* d_out, int out_size) {
    const float* X    = (const float*)d_in[0];
    const float* W    = (const float*)d_in[1];
    const float* b    = (const float*)d_in[2];
    const float* beta = (const float*)d_in[3];
    const float* mean = (const float*)d_in[4];
    const float* var  = (const float*)d_in[5];
    float* out = (float*)d_out;

    const int M = in_sizes[0] / D_IN;   // 32768 (multiple of 128)

    // prep W (transpose + sign + BN fold)
    dim3 pb(32, 8);
    dim3 pg(D_H / 32, D_IN / 32);       // (16, 64)
    qdbn_prep_kernel<<<pg, pb>>>(W, b, beta, mean, var);

    // binarize X: 16 floats per thread
    const int nthreads16 = (M * D_IN) / 16;
    qdbn_binarize_kernel<<<nthreads16 / 256, 256>>>((const float4*)X);

    // GEMM
    cudaFuncSetAttribute(qdbn_imma_kernel,
                         cudaFuncAttributeMaxDynamicSharedMemorySize, SMEM_DYN);
    dim3 grid(D_H / BN, M / BM);        // (4, 256) — N fastest for X L2 reuse
    qdbn_imma_kernel<<<grid, 256, SMEM_DYN>>>(out);
}